// round 1
// baseline (speedup 1.0000x reference)
#include <cuda_runtime.h>
#include <cstdint>

// Problem constants (fixed by setup_inputs)
#define NB   2
#define CIN  32
#define HH   64
#define WW   64
#define LL   (HH * WW)     // 4096
#define OC   32
#define KKK  288           // C * 3 * 3
#define WARPS_PER_BLOCK 8

__global__ __launch_bounds__(WARPS_PER_BLOCK * 32)
void conv_with_filter_kernel(const float* __restrict__ feat,
                             const float4* __restrict__ filt,
                             float* __restrict__ out)
{
    __shared__ float sfeat[WARPS_PER_BLOCK][KKK];

    const int warp = threadIdx.x >> 5;
    const int lane = threadIdx.x & 31;
    const int idx  = blockIdx.x * WARPS_PER_BLOCK + warp;   // 0..8191 = n*4096 + l
    const int n = idx >> 12;
    const int l = idx & 4095;
    const int h = l >> 6;
    const int w = l & 63;

    // ---- stage the 3x3 unfold patch: lane = input channel c ----
    // feat layout [N, C, H, W]; patch ordering k = c*9 + kh*3 + kw
    {
        const float* fbase = feat + (((size_t)n * CIN + lane) * HH) * WW;
        float* s = sfeat[warp] + lane * 9;
        #pragma unroll
        for (int kh = 0; kh < 3; kh++) {
            const int hy = h + kh - 1;
            const bool hin = (hy >= 0) && (hy < HH);
            #pragma unroll
            for (int kw = 0; kw < 3; kw++) {
                const int wx = w + kw - 1;
                float v = 0.0f;
                if (hin && wx >= 0 && wx < WW)
                    v = __ldg(fbase + hy * WW + wx);
                s[kh * 3 + kw] = v;
            }
        }
    }
    __syncwarp();

    // ---- stream filters[n, l, :, :] (288 x 32 fp32, O contiguous) ----
    // lane -> (g, o4): g = k-row group (0..3), o4 = float4 column (0..7)
    const int g  = lane >> 3;
    const int o4 = lane & 7;

    // filters base for this (n,l): idx * 288*32 floats = idx * 2304 float4
    const float4* fw = filt + (size_t)idx * (KKK * OC / 4) + o4;
    const float* s = sfeat[warp];

    float4 acc = make_float4(0.f, 0.f, 0.f, 0.f);

    #pragma unroll 8
    for (int kb = 0; kb < KKK; kb += 4) {
        const int k = kb + g;
        const float  f  = s[k];
        const float4 w4 = fw[(size_t)k * (OC / 4)];   // k*32 floats = k*8 float4
        acc.x = fmaf(f, w4.x, acc.x);
        acc.y = fmaf(f, w4.y, acc.y);
        acc.z = fmaf(f, w4.z, acc.z);
        acc.w = fmaf(f, w4.w, acc.w);
    }

    // ---- reduce across the 4 k-groups (lanes differing in bits 3,4) ----
    #pragma unroll
    for (int off = 8; off <= 16; off <<= 1) {
        acc.x += __shfl_xor_sync(0xffffffffu, acc.x, off);
        acc.y += __shfl_xor_sync(0xffffffffu, acc.y, off);
        acc.z += __shfl_xor_sync(0xffffffffu, acc.z, off);
        acc.w += __shfl_xor_sync(0xffffffffu, acc.w, off);
    }

    // ---- relu + write out[n, o, l], layout [N, OC, L] ----
    if (g == 0) {
        const int obase = o4 * 4;
        float* op = out + ((size_t)n * OC) * LL + l;
        op[(size_t)(obase + 0) * LL] = fmaxf(acc.x, 0.f);
        op[(size_t)(obase + 1) * LL] = fmaxf(acc.y, 0.f);
        op[(size_t)(obase + 2) * LL] = fmaxf(acc.z, 0.f);
        op[(size_t)(obase + 3) * LL] = fmaxf(acc.w, 0.f);
    }
}

extern "C" void kernel_launch(void* const* d_in, const int* in_sizes, int n_in,
                              void* d_out, int out_size)
{
    const float*  feat = (const float*)d_in[0];                // [2,32,64,64]
    const float4* filt = (const float4*)d_in[1];               // [2,4096,288,32]
    float*        out  = (float*)d_out;                        // [2,32,64,64]

    const int total_locs = NB * LL;                            // 8192 warps
    const int blocks = total_locs / WARPS_PER_BLOCK;           // 1024
    conv_with_filter_kernel<<<blocks, WARPS_PER_BLOCK * 32>>>(feat, filt, out);
}

// round 2
// speedup vs baseline: 1.0346x; 1.0346x over previous
#include <cuda_runtime.h>
#include <cstdint>

// Problem constants (fixed by setup_inputs)
#define NB   2
#define CIN  32
#define HH   64
#define WW   64
#define LL   (HH * WW)     // 4096
#define OC   32
#define KKK  288           // C * 3 * 3
#define WARPS_PER_BLOCK 8
#define PF   8             // prefetch pipeline depth (float4 loads in flight)

__global__ __launch_bounds__(WARPS_PER_BLOCK * 32, 4)
void conv_with_filter_kernel(const float* __restrict__ feat,
                             const float4* __restrict__ filt,
                             float* __restrict__ out)
{
    __shared__ float sfeat[WARPS_PER_BLOCK][KKK];

    const int warp = threadIdx.x >> 5;
    const int lane = threadIdx.x & 31;
    const int idx  = blockIdx.x * WARPS_PER_BLOCK + warp;   // 0..8191 = n*4096 + l
    const int n = idx >> 12;
    const int l = idx & 4095;
    const int h = l >> 6;
    const int w = l & 63;

    // ---- stage the 3x3 unfold patch: lane = input channel c ----
    // feat layout [N, C, H, W]; patch ordering k = c*9 + kh*3 + kw
    {
        const float* fbase = feat + (((size_t)n * CIN + lane) * HH) * WW;
        float* s = sfeat[warp] + lane * 9;
        #pragma unroll
        for (int kh = 0; kh < 3; kh++) {
            const int hy = h + kh - 1;
            const bool hin = (hy >= 0) && (hy < HH);
            #pragma unroll
            for (int kw = 0; kw < 3; kw++) {
                const int wx = w + kw - 1;
                float v = 0.0f;
                if (hin && wx >= 0 && wx < WW)
                    v = __ldg(fbase + hy * WW + wx);
                s[kh * 3 + kw] = v;
            }
        }
    }
    __syncwarp();

    // ---- stream filters[n, l, :, :] (288 x 32 fp32, O contiguous) ----
    // lane -> (g, o4): g = k-row group (0..3), o4 = float4 column (0..7)
    const int g  = lane >> 3;
    const int o4 = lane & 7;

    // filters base for this (n,l): idx * 288*32 floats = idx * 2304 float4
    const float4* fw = filt + (size_t)idx * (KKK * OC / 4) + o4;
    const float* s = sfeat[warp] + g;

    float4 acc = make_float4(0.f, 0.f, 0.f, 0.f);

    // 8-deep software pipeline: 8 LDG.128 always in flight per lane
    // row index for pipeline slot j at outer step it: k = (it + j)*4 + g
    float4 buf[PF];
    #pragma unroll
    for (int j = 0; j < PF; j++)
        buf[j] = __ldcs(fw + (size_t)(j * 4 + g) * (OC / 4));

    const int NIT = KKK / 4;  // 72 steps of 4 k-rows each
    #pragma unroll 1
    for (int it = 0; it < NIT; it += PF) {
        #pragma unroll
        for (int j = 0; j < PF; j++) {
            const float4 w4 = buf[j];
            const int knext = (it + j + PF) * 4 + g;   // prefetch 8 steps ahead
            if (knext < KKK)
                buf[j] = __ldcs(fw + (size_t)knext * (OC / 4));
            const float f = s[(it + j) * 4];
            acc.x = fmaf(f, w4.x, acc.x);
            acc.y = fmaf(f, w4.y, acc.y);
            acc.z = fmaf(f, w4.z, acc.z);
            acc.w = fmaf(f, w4.w, acc.w);
        }
    }

    // ---- reduce across the 4 k-groups (lanes differing in bits 3,4) ----
    #pragma unroll
    for (int off = 8; off <= 16; off <<= 1) {
        acc.x += __shfl_xor_sync(0xffffffffu, acc.x, off);
        acc.y += __shfl_xor_sync(0xffffffffu, acc.y, off);
        acc.z += __shfl_xor_sync(0xffffffffu, acc.z, off);
        acc.w += __shfl_xor_sync(0xffffffffu, acc.w, off);
    }

    // ---- relu + write out[n, o, l], layout [N, OC, L] ----
    if (g == 0) {
        const int obase = o4 * 4;
        float* op = out + ((size_t)n * OC) * LL + l;
        op[(size_t)(obase + 0) * LL] = fmaxf(acc.x, 0.f);
        op[(size_t)(obase + 1) * LL] = fmaxf(acc.y, 0.f);
        op[(size_t)(obase + 2) * LL] = fmaxf(acc.z, 0.f);
        op[(size_t)(obase + 3) * LL] = fmaxf(acc.w, 0.f);
    }
}

extern "C" void kernel_launch(void* const* d_in, const int* in_sizes, int n_in,
                              void* d_out, int out_size)
{
    const float*  feat = (const float*)d_in[0];                // [2,32,64,64]
    const float4* filt = (const float4*)d_in[1];               // [2,4096,288,32]
    float*        out  = (float*)d_out;                        // [2,32,64,64]

    const int total_locs = NB * LL;                            // 8192 warps
    const int blocks = total_locs / WARPS_PER_BLOCK;           // 1024
    conv_with_filter_kernel<<<blocks, WARPS_PER_BLOCK * 32>>>(feat, filt, out);
}

// round 3
// speedup vs baseline: 1.0485x; 1.0134x over previous
#include <cuda_runtime.h>
#include <cstdint>

// Problem constants (fixed by setup_inputs)
#define NB   2
#define CIN  32
#define HH   64
#define WW   64
#define LL   (HH * WW)     // 4096
#define OC   32
#define KKK  288           // C * 3 * 3
#define WARPS_PER_BLOCK 8
#define PF   8             // prefetch pipeline depth (float4 loads in flight)

__global__ __launch_bounds__(WARPS_PER_BLOCK * 32, 4)
void conv_with_filter_kernel(const float* __restrict__ feat,
                             const float4* __restrict__ filt,
                             float* __restrict__ out)
{
    __shared__ float sfeat[WARPS_PER_BLOCK][KKK];

    const int warp = threadIdx.x >> 5;
    const int lane = threadIdx.x & 31;
    const int idx  = blockIdx.x * WARPS_PER_BLOCK + warp;   // 0..8191 = n*4096 + l
    const int n = idx >> 12;
    const int l = idx & 4095;
    const int h = l >> 6;
    const int w = l & 63;

    // ---- stage the 3x3 unfold patch: lane = input channel c ----
    // feat layout [N, C, H, W]; patch ordering k = c*9 + kh*3 + kw
    {
        const float* fbase = feat + (((size_t)n * CIN + lane) * HH) * WW;
        float* s = sfeat[warp] + lane * 9;
        #pragma unroll
        for (int kh = 0; kh < 3; kh++) {
            const int hy = h + kh - 1;
            const bool hin = (hy >= 0) && (hy < HH);
            #pragma unroll
            for (int kw = 0; kw < 3; kw++) {
                const int wx = w + kw - 1;
                float v = 0.0f;
                if (hin && wx >= 0 && wx < WW)
                    v = __ldg(fbase + hy * WW + wx);
                s[kh * 3 + kw] = v;
            }
        }
    }
    __syncwarp();

    // ---- stream filters[n, l, :, :] (288 x 32 fp32, O contiguous) ----
    // lane -> (g, o4): g = k-row group (0..3), o4 = float4 column (0..7)
    const int g  = lane >> 3;
    const int o4 = lane & 7;

    // filters base for this (n,l): idx * 288*32 floats = idx * 2304 float4
    const float4* fw = filt + (size_t)idx * (KKK * OC / 4) + o4;
    const float* s = sfeat[warp] + g;

    float4 acc = make_float4(0.f, 0.f, 0.f, 0.f);

    // 8-deep software pipeline: 8 LDG.128 always in flight per lane
    // row index for pipeline slot j at outer step it: k = (it + j)*4 + g
    float4 buf[PF];
    #pragma unroll
    for (int j = 0; j < PF; j++)
        buf[j] = __ldcs(fw + (size_t)(j * 4 + g) * (OC / 4));

    const int NIT = KKK / 4;  // 72 steps of 4 k-rows each
    #pragma unroll 1
    for (int it = 0; it < NIT; it += PF) {
        #pragma unroll
        for (int j = 0; j < PF; j++) {
            const float4 w4 = buf[j];
            const int knext = (it + j + PF) * 4 + g;   // prefetch 8 steps ahead
            if (knext < KKK)
                buf[j] = __ldcs(fw + (size_t)knext * (OC / 4));
            const float f = s[(it + j) * 4];
            acc.x = fmaf(f, w4.x, acc.x);
            acc.y = fmaf(f, w4.y, acc.y);
            acc.z = fmaf(f, w4.z, acc.z);
            acc.w = fmaf(f, w4.w, acc.w);
        }
    }

    // ---- reduce across the 4 k-groups (lanes differing in bits 3,4) ----
    #pragma unroll
    for (int off = 8; off <= 16; off <<= 1) {
        acc.x += __shfl_xor_sync(0xffffffffu, acc.x, off);
        acc.y += __shfl_xor_sync(0xffffffffu, acc.y, off);
        acc.z += __shfl_xor_sync(0xffffffffu, acc.z, off);
        acc.w += __shfl_xor_sync(0xffffffffu, acc.w, off);
    }

    // ---- relu + write out[n, o, l], layout [N, OC, L] ----
    if (g == 0) {
        const int obase = o4 * 4;
        float* op = out + ((size_t)n * OC) * LL + l;
        op[(size_t)(obase + 0) * LL] = fmaxf(acc.x, 0.f);
        op[(size_t)(obase + 1) * LL] = fmaxf(acc.y, 0.f);
        op[(size_t)(obase + 2) * LL] = fmaxf(acc.z, 0.f);
        op[(size_t)(obase + 3) * LL] = fmaxf(acc.w, 0.f);
    }
}

extern "C" void kernel_launch(void* const* d_in, const int* in_sizes, int n_in,
                              void* d_out, int out_size)
{
    const float*  feat = (const float*)d_in[0];                // [2,32,64,64]
    const float4* filt = (const float4*)d_in[1];               // [2,4096,288,32]
    float*        out  = (float*)d_out;                        // [2,32,64,64]

    const int total_locs = NB * LL;                            // 8192 warps
    const int blocks = total_locs / WARPS_PER_BLOCK;           // 1024
    conv_with_filter_kernel<<<blocks, WARPS_PER_BLOCK * 32>>>(feat, filt, out);
}

// round 4
// speedup vs baseline: 1.2056x; 1.1499x over previous
#include <cuda_runtime.h>
#include <cstdint>

// Problem constants (fixed by setup_inputs)
#define NB    2
#define CIN   32
#define HH    64
#define WW    64
#define LL    (HH * WW)     // 4096
#define OC    32
#define KKK   288           // C * 3 * 3
#define NCHUNK 4            // K-split per location
#define KC    (KKK / NCHUNK)        // 72 k-rows per chunk
#define NITC  (KC / 4)              // 18 pipeline steps per chunk
#define PF    8                     // loads in flight per lane
#define LOCS_PER_BLOCK 4
#define THREADS (LOCS_PER_BLOCK * NCHUNK * 32)   // 512

__global__ __launch_bounds__(THREADS, 2)
void conv_with_filter_kernel(const float* __restrict__ feat,
                             const float4* __restrict__ filt,
                             float* __restrict__ out)
{
    __shared__ float sfeat[LOCS_PER_BLOCK][KKK];           // 4 x 288
    __shared__ float sacc[LOCS_PER_BLOCK][NCHUNK][OC];     // 4 x 4 x 32

    const int tid  = threadIdx.x;
    const int warp = tid >> 5;
    const int lane = tid & 31;

    const int idx0 = blockIdx.x * LOCS_PER_BLOCK;          // first location idx
    const int n    = idx0 >> 12;                           // same n for whole block
    const int lbase = idx0 & 4095;

    // ---- cooperative staging of 4 unfold patches (4 x 288 floats) ----
    // patch ordering k = c*9 + kh*3 + kw
    #pragma unroll
    for (int v = tid; v < LOCS_PER_BLOCK * KKK; v += THREADS) {
        const int loc = v / KKK;
        const int k   = v % KKK;
        const int c   = k / 9;
        const int r   = k % 9;
        const int kh  = r / 3;
        const int kw  = r % 3;
        const int l   = lbase + loc;
        const int hy  = (l >> 6) + kh - 1;
        const int wx  = (l & 63) + kw - 1;
        float val = 0.0f;
        if (hy >= 0 && hy < HH && wx >= 0 && wx < WW)
            val = __ldg(feat + (((size_t)n * CIN + c) * HH + hy) * WW + wx);
        sfeat[loc][k] = val;
    }
    __syncthreads();

    // ---- each warp streams one 72-row chunk of filters[n,l,:,:] ----
    const int loc   = warp >> 2;        // 0..3
    const int chunk = warp & 3;         // 0..3
    const int g  = lane >> 3;           // k-row within group of 4
    const int o4 = lane & 7;            // float4 column (8 cols = 32 outputs)

    const int idx = idx0 + loc;
    const float4* fw = filt + (size_t)idx * (KKK * OC / 4) + o4;
    const float* s = sfeat[loc];
    const int kstart = chunk * KC;

    float4 buf[PF];
    #pragma unroll
    for (int j = 0; j < PF; j++)
        buf[j] = __ldcs(fw + (size_t)(kstart + j * 4 + g) * (OC / 4));

    float4 acc = make_float4(0.f, 0.f, 0.f, 0.f);

    #pragma unroll
    for (int step = 0; step < NITC; step++) {
        const float4 w4 = buf[step & (PF - 1)];
        if (step < NITC - PF)
            buf[step & (PF - 1)] =
                __ldcs(fw + (size_t)(kstart + (step + PF) * 4 + g) * (OC / 4));
        const float f = s[kstart + step * 4 + g];
        acc.x = fmaf(f, w4.x, acc.x);
        acc.y = fmaf(f, w4.y, acc.y);
        acc.z = fmaf(f, w4.z, acc.z);
        acc.w = fmaf(f, w4.w, acc.w);
    }

    // ---- reduce across the 4 k-row groups within the warp ----
    #pragma unroll
    for (int off = 8; off <= 16; off <<= 1) {
        acc.x += __shfl_xor_sync(0xffffffffu, acc.x, off);
        acc.y += __shfl_xor_sync(0xffffffffu, acc.y, off);
        acc.z += __shfl_xor_sync(0xffffffffu, acc.z, off);
        acc.w += __shfl_xor_sync(0xffffffffu, acc.w, off);
    }

    if (g == 0) {
        float4* sa = reinterpret_cast<float4*>(sacc[loc][chunk]);
        sa[o4] = acc;
    }
    __syncthreads();

    // ---- combine 4 chunk partials, relu, coalesced store ----
    // out layout [N, OC, L]; 4 consecutive l per o -> 16B contiguous stores
    if (tid < OC * LOCS_PER_BLOCK) {
        const int o  = tid >> 2;        // 0..31
        const int lc = tid & 3;         // 0..3
        float sum = sacc[lc][0][o] + sacc[lc][1][o] + sacc[lc][2][o] + sacc[lc][3][o];
        out[((size_t)n * OC + o) * LL + lbase + lc] = fmaxf(sum, 0.f);
    }
}

extern "C" void kernel_launch(void* const* d_in, const int* in_sizes, int n_in,
                              void* d_out, int out_size)
{
    const float*  feat = (const float*)d_in[0];                // [2,32,64,64]
    const float4* filt = (const float4*)d_in[1];               // [2,4096,288,32]
    float*        out  = (float*)d_out;                        // [2,32,64,64]

    const int blocks = NB * LL / LOCS_PER_BLOCK;               // 2048
    conv_with_filter_kernel<<<blocks, THREADS>>>(feat, filt, out);
}

// round 5
// speedup vs baseline: 1.2065x; 1.0007x over previous
#include <cuda_runtime.h>
#include <cstdint>

// Problem constants (fixed by setup_inputs)
#define NB    2
#define CIN   32
#define HH    64
#define WW    64
#define LL    (HH * WW)     // 4096
#define OC    32
#define KKK   288           // C * 3 * 3
#define NCHUNK 4                    // K-split per location
#define KC    (KKK / NCHUNK)        // 72 k-rows per chunk
#define NITC  (KC / 4)              // 18 pipeline steps per chunk
#define PF    4                     // loads in flight per lane
#define LOCS_PER_BLOCK 2
#define THREADS (LOCS_PER_BLOCK * NCHUNK * 32)   // 256

__global__ __launch_bounds__(THREADS, 6)
void conv_with_filter_kernel(const float* __restrict__ feat,
                             const float4* __restrict__ filt,
                             float* __restrict__ out)
{
    __shared__ float sfeat[LOCS_PER_BLOCK][KKK];           // 2 x 288
    __shared__ float sacc[LOCS_PER_BLOCK][NCHUNK][OC];     // 2 x 4 x 32

    const int tid  = threadIdx.x;
    const int warp = tid >> 5;
    const int lane = tid & 31;

    const int idx0 = blockIdx.x * LOCS_PER_BLOCK;          // first location idx
    const int n    = idx0 >> 12;                           // same n for whole block
    const int lbase = idx0 & 4095;

    // ---- cooperative staging of the unfold patches (2 x 288 floats) ----
    // patch ordering k = c*9 + kh*3 + kw
    #pragma unroll
    for (int v = tid; v < LOCS_PER_BLOCK * KKK; v += THREADS) {
        const int loc = v / KKK;
        const int k   = v % KKK;
        const int c   = k / 9;
        const int r   = k % 9;
        const int kh  = r / 3;
        const int kw  = r % 3;
        const int l   = lbase + loc;
        const int hy  = (l >> 6) + kh - 1;
        const int wx  = (l & 63) + kw - 1;
        float val = 0.0f;
        if (hy >= 0 && hy < HH && wx >= 0 && wx < WW)
            val = __ldg(feat + (((size_t)n * CIN + c) * HH + hy) * WW + wx);
        sfeat[loc][k] = val;
    }
    __syncthreads();

    // ---- each warp streams one 72-row chunk of filters[n,l,:,:] ----
    const int loc   = warp >> 2;        // 0..1
    const int chunk = warp & 3;         // 0..3
    const int g  = lane >> 3;           // k-row within group of 4
    const int o4 = lane & 7;            // float4 column (8 cols = 32 outputs)

    const int idx = idx0 + loc;
    const int kstart = chunk * KC;
    // lane's first load address; each step advances by 4 k-rows = 32 float4
    const float4* fw = filt + (size_t)idx * (KKK * OC / 4)
                            + (size_t)(kstart + g) * (OC / 4) + o4;
    const float* s = sfeat[loc] + kstart + g;

    float4 buf[PF];
    #pragma unroll
    for (int j = 0; j < PF; j++)
        buf[j] = __ldcs(fw + j * 32);

    const float4* fpf = fw + PF * 32;   // prefetch cursor
    float4 acc = make_float4(0.f, 0.f, 0.f, 0.f);

    #pragma unroll
    for (int step = 0; step < NITC; step++) {
        const float4 w4 = buf[step % PF];
        if (step < NITC - PF)
            buf[step % PF] = __ldcs(fpf + step * 32);
        const float f = s[step * 4];
        acc.x = fmaf(f, w4.x, acc.x);
        acc.y = fmaf(f, w4.y, acc.y);
        acc.z = fmaf(f, w4.z, acc.z);
        acc.w = fmaf(f, w4.w, acc.w);
    }

    // ---- reduce across the 4 k-row groups within the warp ----
    #pragma unroll
    for (int off = 8; off <= 16; off <<= 1) {
        acc.x += __shfl_xor_sync(0xffffffffu, acc.x, off);
        acc.y += __shfl_xor_sync(0xffffffffu, acc.y, off);
        acc.z += __shfl_xor_sync(0xffffffffu, acc.z, off);
        acc.w += __shfl_xor_sync(0xffffffffu, acc.w, off);
    }

    if (g == 0) {
        float4* sa = reinterpret_cast<float4*>(sacc[loc][chunk]);
        sa[o4] = acc;
    }
    __syncthreads();

    // ---- combine 4 chunk partials, relu, store ----
    // out layout [N, OC, L]
    if (tid < OC * LOCS_PER_BLOCK) {
        const int o  = tid >> 1;        // 0..31
        const int lc = tid & 1;         // 0..1
        float sum = sacc[lc][0][o] + sacc[lc][1][o] + sacc[lc][2][o] + sacc[lc][3][o];
        out[((size_t)n * OC + o) * LL + lbase + lc] = fmaxf(sum, 0.f);
    }
}

extern "C" void kernel_launch(void* const* d_in, const int* in_sizes, int n_in,
                              void* d_out, int out_size)
{
    const float*  feat = (const float*)d_in[0];                // [2,32,64,64]
    const float4* filt = (const float4*)d_in[1];               // [2,4096,288,32]
    float*        out  = (float*)d_out;                        // [2,32,64,64]

    const int blocks = NB * LL / LOCS_PER_BLOCK;               // 4096
    conv_with_filter_kernel<<<blocks, THREADS>>>(feat, filt, out);
}